// round 1
// baseline (speedup 1.0000x reference)
#include <cuda_runtime.h>
#include <cuda_bf16.h>
#include <math.h>

// Router: logits = x @ W^T (N=16384, D=2048, E=64), softmax over E,
// top-2 (tie -> lower index), weights renormalized.
// Output (fp32, concatenated): probs [N*64] | indices [N*2] | weights [N*2]

#define BM 64
#define BN 64
#define BK 16
#define D_DIM 2048
#define E_DIM 64
#define THREADS 256

__global__ __launch_bounds__(THREADS, 1)
void router_kernel(const float* __restrict__ x,
                   const float* __restrict__ W,
                   float* __restrict__ probs_out,
                   float* __restrict__ idx_out,
                   float* __restrict__ w_out)
{
    __shared__ float xs[BK][BM];      // transposed x tile
    __shared__ float ws[BK][BN];      // transposed W tile
    __shared__ float ls[BM][BN + 2];  // logits staging (padded)

    const int tid = threadIdx.x;
    const int m0  = blockIdx.x * BM;

    // 4x4 micro-tile mapping: 16x16 thread grid
    const int tx = tid & 15;   // expert group
    const int ty = tid >> 4;   // row group

    // load mapping: each thread loads one float4
    const int lr = tid >> 2;         // row within tile (0..63)
    const int lk = (tid & 3) * 4;    // k offset within BK

    float acc[4][4];
#pragma unroll
    for (int i = 0; i < 4; i++)
#pragma unroll
        for (int j = 0; j < 4; j++) acc[i][j] = 0.0f;

    const float* xrow = x + (size_t)(m0 + lr) * D_DIM + lk;
    const float* wrow = W + (size_t)lr * D_DIM + lk;

    for (int kb = 0; kb < D_DIM; kb += BK) {
        float4 xv = *(const float4*)(xrow + kb);
        float4 wv = *(const float4*)(wrow + kb);

        __syncthreads();   // previous tile fully consumed
        xs[lk + 0][lr] = xv.x;
        xs[lk + 1][lr] = xv.y;
        xs[lk + 2][lr] = xv.z;
        xs[lk + 3][lr] = xv.w;
        ws[lk + 0][lr] = wv.x;
        ws[lk + 1][lr] = wv.y;
        ws[lk + 2][lr] = wv.z;
        ws[lk + 3][lr] = wv.w;
        __syncthreads();

#pragma unroll
        for (int k = 0; k < BK; k++) {
            float4 a = *(const float4*)&xs[k][ty * 4];
            float4 b = *(const float4*)&ws[k][tx * 4];
            float av[4] = {a.x, a.y, a.z, a.w};
            float bv[4] = {b.x, b.y, b.z, b.w};
#pragma unroll
            for (int i = 0; i < 4; i++)
#pragma unroll
                for (int j = 0; j < 4; j++)
                    acc[i][j] = fmaf(av[i], bv[j], acc[i][j]);
        }
    }

    // stage logits to smem
#pragma unroll
    for (int i = 0; i < 4; i++)
#pragma unroll
        for (int j = 0; j < 4; j++)
            ls[ty * 4 + i][tx * 4 + j] = acc[i][j];
    __syncthreads();

    // Epilogue: one warp per row (8 warps, 64 rows -> 8 rows each)
    const int warp = tid >> 5;
    const int lane = tid & 31;
    const unsigned FULL = 0xFFFFFFFFu;

    for (int r = warp; r < BM; r += 8) {
        float l1 = ls[r][lane];
        float l2 = ls[r][lane + 32];

        // row max
        float m = fmaxf(l1, l2);
#pragma unroll
        for (int off = 16; off > 0; off >>= 1)
            m = fmaxf(m, __shfl_xor_sync(FULL, m, off));

        float e1 = expf(l1 - m);
        float e2 = expf(l2 - m);

        float s = e1 + e2;
#pragma unroll
        for (int off = 16; off > 0; off >>= 1)
            s += __shfl_xor_sync(FULL, s, off);
        float inv = 1.0f / s;

        const int row = m0 + r;
        probs_out[(size_t)row * E_DIM + lane]      = e1 * inv;
        probs_out[(size_t)row * E_DIM + lane + 32] = e2 * inv;

        // per-lane top-2 (tie -> lower index; lane < lane+32 always)
        float v1, v2;
        int i1, i2;
        if (e1 >= e2) { v1 = e1; i1 = lane;      v2 = e2; i2 = lane + 32; }
        else          { v1 = e2; i1 = lane + 32; v2 = e1; i2 = lane; }

        // butterfly merge of top-2 structs
#pragma unroll
        for (int off = 16; off > 0; off >>= 1) {
            float ov1 = __shfl_xor_sync(FULL, v1, off);
            int   oi1 = __shfl_xor_sync(FULL, i1, off);
            float ov2 = __shfl_xor_sync(FULL, v2, off);
            int   oi2 = __shfl_xor_sync(FULL, i2, off);

            bool o_first = (ov1 > v1) || (ov1 == v1 && oi1 < i1);
            float n1, n2;
            int ni1, ni2;
            if (o_first) {
                n1 = ov1; ni1 = oi1;
                bool a = (v1 > ov2) || (v1 == ov2 && i1 < oi2);
                if (a) { n2 = v1;  ni2 = i1;  } else { n2 = ov2; ni2 = oi2; }
            } else {
                n1 = v1; ni1 = i1;
                bool a = (ov1 > v2) || (ov1 == v2 && oi1 < i2);
                if (a) { n2 = ov1; ni2 = oi1; } else { n2 = v2;  ni2 = i2;  }
            }
            v1 = n1; i1 = ni1; v2 = n2; i2 = ni2;
        }

        if (lane == 0) {
            float p1 = v1 * inv;
            float p2 = v2 * inv;
            float denom = p1 + p2 + 1e-9f;
            idx_out[(size_t)row * 2 + 0] = (float)i1;
            idx_out[(size_t)row * 2 + 1] = (float)i2;
            w_out[(size_t)row * 2 + 0]   = p1 / denom;
            w_out[(size_t)row * 2 + 1]   = p2 / denom;
        }
    }
}

extern "C" void kernel_launch(void* const* d_in, const int* in_sizes, int n_in,
                              void* d_out, int out_size)
{
    const float* x = (const float*)d_in[0];
    const float* W = (const float*)d_in[1];
    const int N = in_sizes[0] / D_DIM;   // 16384

    float* out   = (float*)d_out;
    float* probs = out;
    float* idx   = out + (size_t)N * E_DIM;
    float* wts   = out + (size_t)N * E_DIM + (size_t)N * 2;

    dim3 grid(N / BM);
    dim3 block(THREADS);
    router_kernel<<<grid, block>>>(x, W, probs, idx, wts);
}

// round 2
// speedup vs baseline: 1.3693x; 1.3693x over previous
#include <cuda_runtime.h>
#include <cuda_bf16.h>
#include <math.h>

// Router: logits = x @ W^T (N=16384, D=2048, E=64), softmax over E,
// top-2 (tie -> lower index), weights renormalized.
// Output (fp32, concatenated): probs [N*64] | indices [N*2] | weights [N*2]
//
// R2: BM=128 x BN=64 tile, 8x4 micro-tile per thread, packed fma.rn.f32x2
// (2 fp32 FMA per instruction -- full Blackwell fp32 rate), single wave
// (grid=128), register-prefetch double buffering.

#define BM 128
#define BN 64
#define BK 16
#define D_DIM 2048
#define E_DIM 64
#define THREADS 256

typedef unsigned long long u64;

__device__ __forceinline__ u64 pack2(float lo, float hi) {
    u64 r;
    asm("mov.b64 %0, {%1, %2};" : "=l"(r) : "f"(lo), "f"(hi));
    return r;
}
__device__ __forceinline__ void unpack2(u64 v, float& lo, float& hi) {
    asm("mov.b64 {%0, %1}, %2;" : "=f"(lo), "=f"(hi) : "l"(v));
}
#define FMA2(d, a, b) \
    asm("fma.rn.f32x2 %0, %1, %2, %0;" : "+l"(d) : "l"(a), "l"(b))

__global__ __launch_bounds__(THREADS, 1)
void router_kernel(const float* __restrict__ x,
                   const float* __restrict__ W,
                   float* __restrict__ probs_out,
                   float* __restrict__ idx_out,
                   float* __restrict__ w_out)
{
    __shared__ float xs[BK][BM];       // transposed x tile (k-major)
    __shared__ float ws[BK][BN];       // transposed W tile
    __shared__ float ls[BM][BN + 2];   // logits staging (padded)

    const int tid = threadIdx.x;
    const int m0  = blockIdx.x * BM;

    // compute mapping: 16x16 thread grid, 8 rows x 4 cols per thread
    const int tx = tid & 15;    // col group: cols tx*4 .. tx*4+3
    const int ty = tid >> 4;    // row group: rows ty*8 .. ty*8+7

    // load mapping x: thread -> (row = tid>>1, kc = (tid&1)*8), 2 float4
    const int xlr = tid >> 1;
    const int xlk = (tid & 1) * 8;
    // load mapping W: thread -> (row = tid>>2, kc = (tid&3)*4), 1 float4
    const int wlr = tid >> 2;
    const int wlk = (tid & 3) * 4;

    const float* xptr = x + (size_t)(m0 + xlr) * D_DIM + xlk;
    const float* wptr = W + (size_t)wlr * D_DIM + wlk;

    // accumulators: 4 row-pairs x 4 cols, packed f32x2 along rows
    u64 acc[4][4];
    const u64 zz = pack2(0.0f, 0.0f);
#pragma unroll
    for (int i = 0; i < 4; i++)
#pragma unroll
        for (int j = 0; j < 4; j++) acc[i][j] = zz;

    // prefetch tile 0
    float4 px0 = *(const float4*)(xptr);
    float4 px1 = *(const float4*)(xptr + 4);
    float4 pw  = *(const float4*)(wptr);

    for (int kb = 0; kb < D_DIM; kb += BK) {
        __syncthreads();   // previous tile fully consumed
        // store prefetched tile (transposed)
        xs[xlk + 0][xlr] = px0.x;
        xs[xlk + 1][xlr] = px0.y;
        xs[xlk + 2][xlr] = px0.z;
        xs[xlk + 3][xlr] = px0.w;
        xs[xlk + 4][xlr] = px1.x;
        xs[xlk + 5][xlr] = px1.y;
        xs[xlk + 6][xlr] = px1.z;
        xs[xlk + 7][xlr] = px1.w;
        ws[wlk + 0][wlr] = pw.x;
        ws[wlk + 1][wlr] = pw.y;
        ws[wlk + 2][wlr] = pw.z;
        ws[wlk + 3][wlr] = pw.w;
        __syncthreads();

        // prefetch next tile into registers (overlaps with FMA block)
        if (kb + BK < D_DIM) {
            px0 = *(const float4*)(xptr + kb + BK);
            px1 = *(const float4*)(xptr + kb + BK + 4);
            pw  = *(const float4*)(wptr + kb + BK);
        }

#pragma unroll
        for (int k = 0; k < BK; k++) {
            // 8 row values = 4 packed pairs (consecutive floats in smem)
            const u64* ap = (const u64*)&xs[k][ty * 8];
            u64 a0 = ap[0], a1 = ap[1], a2 = ap[2], a3 = ap[3];
            float4 b = *(const float4*)&ws[k][tx * 4];
            u64 b0 = pack2(b.x, b.x);
            u64 b1 = pack2(b.y, b.y);
            u64 b2 = pack2(b.z, b.z);
            u64 b3 = pack2(b.w, b.w);

            FMA2(acc[0][0], a0, b0); FMA2(acc[0][1], a0, b1);
            FMA2(acc[0][2], a0, b2); FMA2(acc[0][3], a0, b3);
            FMA2(acc[1][0], a1, b0); FMA2(acc[1][1], a1, b1);
            FMA2(acc[1][2], a1, b2); FMA2(acc[1][3], a1, b3);
            FMA2(acc[2][0], a2, b0); FMA2(acc[2][1], a2, b1);
            FMA2(acc[2][2], a2, b2); FMA2(acc[2][3], a2, b3);
            FMA2(acc[3][0], a3, b0); FMA2(acc[3][1], a3, b1);
            FMA2(acc[3][2], a3, b2); FMA2(acc[3][3], a3, b3);
        }
    }

    // stage logits to smem
    __syncthreads();
#pragma unroll
    for (int i = 0; i < 4; i++) {
#pragma unroll
        for (int j = 0; j < 4; j++) {
            float lo, hi;
            unpack2(acc[i][j], lo, hi);
            ls[ty * 8 + 2 * i + 0][tx * 4 + j] = lo;
            ls[ty * 8 + 2 * i + 1][tx * 4 + j] = hi;
        }
    }
    __syncthreads();

    // Epilogue: one warp per row (8 warps, 128 rows -> 16 rows each)
    const int warp = tid >> 5;
    const int lane = tid & 31;
    const unsigned FULL = 0xFFFFFFFFu;

    for (int r = warp; r < BM; r += 8) {
        float l1 = ls[r][lane];
        float l2 = ls[r][lane + 32];

        // row max
        float m = fmaxf(l1, l2);
#pragma unroll
        for (int off = 16; off > 0; off >>= 1)
            m = fmaxf(m, __shfl_xor_sync(FULL, m, off));

        float e1 = expf(l1 - m);
        float e2 = expf(l2 - m);

        float s = e1 + e2;
#pragma unroll
        for (int off = 16; off > 0; off >>= 1)
            s += __shfl_xor_sync(FULL, s, off);
        float inv = 1.0f / s;

        const int row = m0 + r;
        probs_out[(size_t)row * E_DIM + lane]      = e1 * inv;
        probs_out[(size_t)row * E_DIM + lane + 32] = e2 * inv;

        // per-lane top-2 (tie -> lower index; lane < lane+32 always)
        float v1, v2;
        int i1, i2;
        if (e1 >= e2) { v1 = e1; i1 = lane;      v2 = e2; i2 = lane + 32; }
        else          { v1 = e2; i1 = lane + 32; v2 = e1; i2 = lane; }

        // butterfly merge of top-2 structs
#pragma unroll
        for (int off = 16; off > 0; off >>= 1) {
            float ov1 = __shfl_xor_sync(FULL, v1, off);
            int   oi1 = __shfl_xor_sync(FULL, i1, off);
            float ov2 = __shfl_xor_sync(FULL, v2, off);
            int   oi2 = __shfl_xor_sync(FULL, i2, off);

            bool o_first = (ov1 > v1) || (ov1 == v1 && oi1 < i1);
            float n1, n2;
            int ni1, ni2;
            if (o_first) {
                n1 = ov1; ni1 = oi1;
                bool a = (v1 > ov2) || (v1 == ov2 && i1 < oi2);
                if (a) { n2 = v1;  ni2 = i1;  } else { n2 = ov2; ni2 = oi2; }
            } else {
                n1 = v1; ni1 = i1;
                bool a = (ov1 > v2) || (ov1 == v2 && oi1 < i2);
                if (a) { n2 = ov1; ni2 = oi1; } else { n2 = v2;  ni2 = i2;  }
            }
            v1 = n1; i1 = ni1; v2 = n2; i2 = ni2;
        }

        if (lane == 0) {
            float p1 = v1 * inv;
            float p2 = v2 * inv;
            float denom = p1 + p2 + 1e-9f;
            idx_out[(size_t)row * 2 + 0] = (float)i1;
            idx_out[(size_t)row * 2 + 1] = (float)i2;
            w_out[(size_t)row * 2 + 0]   = p1 / denom;
            w_out[(size_t)row * 2 + 1]   = p2 / denom;
        }
    }
}

extern "C" void kernel_launch(void* const* d_in, const int* in_sizes, int n_in,
                              void* d_out, int out_size)
{
    const float* x = (const float*)d_in[0];
    const float* W = (const float*)d_in[1];
    const int N = in_sizes[0] / D_DIM;   // 16384

    float* out   = (float*)d_out;
    float* probs = out;
    float* idx   = out + (size_t)N * E_DIM;
    float* wts   = out + (size_t)N * E_DIM + (size_t)N * 2;

    dim3 grid(N / BM);
    dim3 block(THREADS);
    router_kernel<<<grid, block>>>(x, W, probs, idx, wts);
}

// round 5
// speedup vs baseline: 1.4082x; 1.0284x over previous
#include <cuda_runtime.h>
#include <cuda_bf16.h>
#include <cstdint>
#include <math.h>

// Router: logits = x @ W^T (N=16384, D=2048, E=64), softmax, top-2, renorm.
// Output fp32 concat: probs [N*64] | indices [N*2] | weights [N*2]
//
// R5: mma.sync m16n8k8 tf32 with 3xTF32 split. Chunk-local accumulators
// (zeroed per K=32 chunk, folded into master acc with IEEE FFMA) to kill
// tensor-core truncation bias. Top-4 candidates + ambiguity flag per row;
// pass-2 kernel recomputes flagged rows' candidate logits in exact fp32
// and rewrites indices/weights.

#define D_DIM 2048
#define E_DIM 64
#define BM 128
#define BN 64
#define BK 32
#define THREADS 512
#define NCHUNK (D_DIM / BK)   // 64
#define N_ROWS 16384
#define TAU 2e-4f

#define A_STRIDE 36
#define B_STRIDE 36
#define A_FLOATS (BM * A_STRIDE)
#define B_FLOATS (BN * B_STRIDE)
#define STAGE_FLOATS (A_FLOATS + B_FLOATS)
#define SMEM_BYTES (2 * STAGE_FLOATS * 4)

__device__ int g_flags[N_ROWS];
__device__ int g_cand[N_ROWS][4];

__device__ __forceinline__ uint32_t smem_u32(const void* p) {
    uint32_t a;
    asm("{ .reg .u64 t; cvta.to.shared.u64 t, %1; cvt.u32.u64 %0, t; }" : "=r"(a) : "l"(p));
    return a;
}
__device__ __forceinline__ uint32_t tf32_hi(float x) {
    uint32_t r;
    asm("cvt.rna.tf32.f32 %0, %1;" : "=r"(r) : "f"(x));
    return r;
}
__device__ __forceinline__ void cp_async16(uint32_t dst, const void* src) {
    asm volatile("cp.async.ca.shared.global [%0], [%1], 16;" :: "r"(dst), "l"(src) : "memory");
}
__device__ __forceinline__ void cp_commit() {
    asm volatile("cp.async.commit_group;" ::: "memory");
}
__device__ __forceinline__ void cp_wait1() {
    asm volatile("cp.async.wait_group 1;" ::: "memory");
}
__device__ __forceinline__ void cp_wait0() {
    asm volatile("cp.async.wait_group 0;" ::: "memory");
}
__device__ __forceinline__ void mma_tf32(float* c,
                                         uint32_t a0, uint32_t a1, uint32_t a2, uint32_t a3,
                                         uint32_t b0, uint32_t b1) {
    asm volatile(
        "mma.sync.aligned.m16n8k8.row.col.f32.tf32.tf32.f32 "
        "{%0,%1,%2,%3}, {%4,%5,%6,%7}, {%8,%9}, {%0,%1,%2,%3};"
        : "+f"(c[0]), "+f"(c[1]), "+f"(c[2]), "+f"(c[3])
        : "r"(a0), "r"(a1), "r"(a2), "r"(a3), "r"(b0), "r"(b1));
}

__global__ __launch_bounds__(THREADS, 1)
void router_kernel(const float* __restrict__ x,
                   const float* __restrict__ W,
                   float* __restrict__ probs_out,
                   float* __restrict__ idx_out,
                   float* __restrict__ w_out)
{
    extern __shared__ float smem[];

    const int tid  = threadIdx.x;
    const int wid  = tid >> 5;
    const int lane = tid & 31;
    const int m0   = blockIdx.x * BM;

    const int wm = wid & 3;
    const int wn = wid >> 2;
    const int wr = wm * 32;
    const int wc = wn * 16;

    const int qr = lane >> 2;
    const int qc = lane & 3;

    const int af0 = tid;
    const int af1 = tid + 512;
    const int bf  = tid;

    float accm[2][2][4];
#pragma unroll
    for (int i = 0; i < 2; i++)
#pragma unroll
        for (int j = 0; j < 2; j++)
#pragma unroll
            for (int k = 0; k < 4; k++) accm[i][j][k] = 0.0f;

    auto issue_stage = [&](int chunk, int s) {
        float* As = smem + s * STAGE_FLOATS;
        float* Bs = As + A_FLOATS;
        const int kb = chunk * BK;
        {
            int r = af0 >> 3, c4 = (af0 & 7) * 4;
            cp_async16(smem_u32(As + r * A_STRIDE + c4),
                       x + (size_t)(m0 + r) * D_DIM + kb + c4);
            r = af1 >> 3; c4 = (af1 & 7) * 4;
            cp_async16(smem_u32(As + r * A_STRIDE + c4),
                       x + (size_t)(m0 + r) * D_DIM + kb + c4);
        }
        {
            int r = bf >> 3, c4 = (bf & 7) * 4;
            cp_async16(smem_u32(Bs + r * B_STRIDE + c4),
                       W + (size_t)r * D_DIM + kb + c4);
        }
        cp_commit();
    };

    issue_stage(0, 0);

    for (int c = 0; c < NCHUNK; c++) {
        const int s = c & 1;
        if (c + 1 < NCHUNK) {
            issue_stage(c + 1, s ^ 1);
            cp_wait1();
        } else {
            cp_wait0();
        }
        __syncthreads();

        const float* As = smem + s * STAGE_FLOATS;
        const float* Bs = As + A_FLOATS;

        // chunk-local accumulators (bias containment)
        float accc[2][2][4];
#pragma unroll
        for (int i = 0; i < 2; i++)
#pragma unroll
            for (int j = 0; j < 2; j++)
#pragma unroll
                for (int k = 0; k < 4; k++) accc[i][j][k] = 0.0f;

#pragma unroll
        for (int ks = 0; ks < 4; ks++) {
            const int k0 = ks * 8;

            uint32_t ah[2][4], al[2][4];
#pragma unroll
            for (int mt = 0; mt < 2; mt++) {
                const float* ap = As + (wr + mt * 16 + qr) * A_STRIDE + k0 + qc;
                float v0 = ap[0];
                float v1 = ap[8 * A_STRIDE];
                float v2 = ap[4];
                float v3 = ap[8 * A_STRIDE + 4];
                ah[mt][0] = tf32_hi(v0);
                ah[mt][1] = tf32_hi(v1);
                ah[mt][2] = tf32_hi(v2);
                ah[mt][3] = tf32_hi(v3);
                al[mt][0] = tf32_hi(v0 - __uint_as_float(ah[mt][0]));
                al[mt][1] = tf32_hi(v1 - __uint_as_float(ah[mt][1]));
                al[mt][2] = tf32_hi(v2 - __uint_as_float(ah[mt][2]));
                al[mt][3] = tf32_hi(v3 - __uint_as_float(ah[mt][3]));
            }

            uint32_t bh[2][2], bl[2][2];
#pragma unroll
            for (int nt = 0; nt < 2; nt++) {
                const float* bp = Bs + (wc + nt * 8 + qr) * B_STRIDE + k0 + qc;
                float v0 = bp[0];
                float v1 = bp[4];
                bh[nt][0] = tf32_hi(v0);
                bh[nt][1] = tf32_hi(v1);
                bl[nt][0] = tf32_hi(v0 - __uint_as_float(bh[nt][0]));
                bl[nt][1] = tf32_hi(v1 - __uint_as_float(bh[nt][1]));
            }

#pragma unroll
            for (int mt = 0; mt < 2; mt++)
#pragma unroll
                for (int nt = 0; nt < 2; nt++) {
                    mma_tf32(accc[mt][nt], ah[mt][0], ah[mt][1], ah[mt][2], ah[mt][3],
                             bh[nt][0], bh[nt][1]);
                    mma_tf32(accc[mt][nt], ah[mt][0], ah[mt][1], ah[mt][2], ah[mt][3],
                             bl[nt][0], bl[nt][1]);
                    mma_tf32(accc[mt][nt], al[mt][0], al[mt][1], al[mt][2], al[mt][3],
                             bh[nt][0], bh[nt][1]);
                }
        }

        // fold into master (IEEE RN adds)
#pragma unroll
        for (int i = 0; i < 2; i++)
#pragma unroll
            for (int j = 0; j < 2; j++)
#pragma unroll
                for (int k = 0; k < 4; k++) accm[i][j][k] += accc[i][j][k];

        __syncthreads();
    }

    // ---- stage logits into smem overlay ----
    float (*ls)[E_DIM + 2] = (float (*)[E_DIM + 2])smem;
#pragma unroll
    for (int mt = 0; mt < 2; mt++)
#pragma unroll
        for (int nt = 0; nt < 2; nt++) {
            int r  = wr + mt * 16 + qr;
            int cc = wc + nt * 8 + qc * 2;
            ls[r][cc]         = accm[mt][nt][0];
            ls[r][cc + 1]     = accm[mt][nt][1];
            ls[r + 8][cc]     = accm[mt][nt][2];
            ls[r + 8][cc + 1] = accm[mt][nt][3];
        }
    __syncthreads();

    // ---- epilogue: one warp per row ----
    const unsigned FULL = 0xFFFFFFFFu;

    auto wtop2 = [&](float pa, int ia, float pb, int ib,
                     float& V1, int& I1, float& V2, int& I2) {
        float v1, v2; int i1, i2;
        if (pa >= pb) { v1 = pa; i1 = ia; v2 = pb; i2 = ib; }
        else          { v1 = pb; i1 = ib; v2 = pa; i2 = ia; }
#pragma unroll
        for (int off = 16; off > 0; off >>= 1) {
            float ov1 = __shfl_xor_sync(FULL, v1, off);
            int   oi1 = __shfl_xor_sync(FULL, i1, off);
            float ov2 = __shfl_xor_sync(FULL, v2, off);
            int   oi2 = __shfl_xor_sync(FULL, i2, off);
            bool o_first = (ov1 > v1) || (ov1 == v1 && oi1 < i1);
            float n1, n2; int ni1, ni2;
            if (o_first) {
                n1 = ov1; ni1 = oi1;
                bool a = (v1 > ov2) || (v1 == ov2 && i1 < oi2);
                if (a) { n2 = v1;  ni2 = i1;  } else { n2 = ov2; ni2 = oi2; }
            } else {
                n1 = v1; ni1 = i1;
                bool a = (ov1 > v2) || (ov1 == v2 && oi1 < i2);
                if (a) { n2 = ov1; ni2 = oi1; } else { n2 = v2;  ni2 = i2;  }
            }
            v1 = n1; i1 = ni1; v2 = n2; i2 = ni2;
        }
        V1 = v1; I1 = i1; V2 = v2; I2 = i2;
    };

    for (int r = wid; r < BM; r += 16) {
        float l1 = ls[r][lane];
        float l2 = ls[r][lane + 32];

        float m = fmaxf(l1, l2);
#pragma unroll
        for (int off = 16; off > 0; off >>= 1)
            m = fmaxf(m, __shfl_xor_sync(FULL, m, off));

        float e1 = expf(l1 - m);
        float e2 = expf(l2 - m);

        float s = e1 + e2;
#pragma unroll
        for (int off = 16; off > 0; off >>= 1)
            s += __shfl_xor_sync(FULL, s, off);
        float inv = 1.0f / s;

        float pa = e1 * inv;
        float pb = e2 * inv;

        const int row = m0 + r;
        probs_out[(size_t)row * E_DIM + lane]      = pa;
        probs_out[(size_t)row * E_DIM + lane + 32] = pb;

        float v1, v2, v3, v4;
        int i1, i2, i3, i4;
        wtop2(pa, lane, pb, lane + 32, v1, i1, v2, i2);

        float pa2 = (lane == i1 || lane == i2) ? -1.0f : pa;
        float pb2 = (lane + 32 == i1 || lane + 32 == i2) ? -1.0f : pb;
        wtop2(pa2, lane, pb2, lane + 32, v3, i3, v4, i4);

        if (lane == 0) {
            float denom = v1 + v2 + 1e-9f;
            idx_out[(size_t)row * 2 + 0] = (float)i1;
            idx_out[(size_t)row * 2 + 1] = (float)i2;
            w_out[(size_t)row * 2 + 0]   = v1 / denom;
            w_out[(size_t)row * 2 + 1]   = v2 / denom;
            g_cand[row][0] = i1;
            g_cand[row][1] = i2;
            g_cand[row][2] = i3;
            g_cand[row][3] = i4;
            g_flags[row] = ((v1 - v2) < TAU) || ((v2 - v3) < TAU) ? 1 : 0;
        }
    }
}

// Pass 2: exact fp32 re-evaluation of 4 candidate logits for flagged rows.
__global__ __launch_bounds__(256, 1)
void refine_kernel(const float* __restrict__ x,
                   const float* __restrict__ W,
                   float* __restrict__ idx_out,
                   float* __restrict__ w_out)
{
    const int warp = threadIdx.x >> 5;
    const int lane = threadIdx.x & 31;
    const int row  = blockIdx.x * 8 + warp;
    if (row >= N_ROWS) return;
    if (g_flags[row] == 0) return;

    int c0 = g_cand[row][0], c1 = g_cand[row][1];
    int c2 = g_cand[row][2], c3 = g_cand[row][3];

    const float* xr = x + (size_t)row * D_DIM;
    const float* w0 = W + (size_t)c0 * D_DIM;
    const float* w1 = W + (size_t)c1 * D_DIM;
    const float* w2 = W + (size_t)c2 * D_DIM;
    const float* w3 = W + (size_t)c3 * D_DIM;

    float d0 = 0.f, d1 = 0.f, d2 = 0.f, d3 = 0.f;
    for (int k = lane * 4; k < D_DIM; k += 128) {
        float4 xv = *(const float4*)(xr + k);
        float4 a  = *(const float4*)(w0 + k);
        float4 b  = *(const float4*)(w1 + k);
        float4 cc = *(const float4*)(w2 + k);
        float4 dd = *(const float4*)(w3 + k);
        d0 = fmaf(xv.x, a.x,  fmaf(xv.y, a.y,  fmaf(xv.z, a.z,  fmaf(xv.w, a.w,  d0))));
        d1 = fmaf(xv.x, b.x,  fmaf(xv.y, b.y,  fmaf(xv.z, b.z,  fmaf(xv.w, b.w,  d1))));
        d2 = fmaf(xv.x, cc.x, fmaf(xv.y, cc.y, fmaf(xv.z, cc.z, fmaf(xv.w, cc.w, d2))));
        d3 = fmaf(xv.x, dd.x, fmaf(xv.y, dd.y, fmaf(xv.z, dd.z, fmaf(xv.w, dd.w, d3))));
    }
    const unsigned FULL = 0xFFFFFFFFu;
#pragma unroll
    for (int off = 16; off > 0; off >>= 1) {
        d0 += __shfl_xor_sync(FULL, d0, off);
        d1 += __shfl_xor_sync(FULL, d1, off);
        d2 += __shfl_xor_sync(FULL, d2, off);
        d3 += __shfl_xor_sync(FULL, d3, off);
    }

    if (lane == 0) {
        float l[4]  = {d0, d1, d2, d3};
        int   id[4] = {c0, c1, c2, c3};
        // selection sort (desc, tie -> lower index), first 2 positions
#pragma unroll
        for (int i = 0; i < 2; i++) {
            int best = i;
#pragma unroll
            for (int j = i + 1; j < 4; j++) {
                if ((l[j] > l[best]) || (l[j] == l[best] && id[j] < id[best])) best = j;
            }
            float tl = l[i]; l[i] = l[best]; l[best] = tl;
            int ti = id[i]; id[i] = id[best]; id[best] = ti;
        }
        float m  = fmaxf(l[0], l[1]);
        float e1 = expf(l[0] - m);
        float e2 = expf(l[1] - m);
        float w1v = e1 / (e1 + e2);
        idx_out[(size_t)row * 2 + 0] = (float)id[0];
        idx_out[(size_t)row * 2 + 1] = (float)id[1];
        w_out[(size_t)row * 2 + 0]   = w1v;
        w_out[(size_t)row * 2 + 1]   = 1.0f - w1v;
    }
}

extern "C" void kernel_launch(void* const* d_in, const int* in_sizes, int n_in,
                              void* d_out, int out_size)
{
    const float* x = (const float*)d_in[0];
    const float* W = (const float*)d_in[1];
    const int N = in_sizes[0] / D_DIM;   // 16384

    float* out   = (float*)d_out;
    float* probs = out;
    float* idx   = out + (size_t)N * E_DIM;
    float* wts   = out + (size_t)N * E_DIM + (size_t)N * 2;

    cudaFuncSetAttribute(router_kernel,
                         cudaFuncAttributeMaxDynamicSharedMemorySize, SMEM_BYTES);

    router_kernel<<<N / BM, THREADS, SMEM_BYTES>>>(x, W, probs, idx, wts);
    refine_kernel<<<(N + 7) / 8, 256>>>(x, W, idx, wts);
}

// round 6
// speedup vs baseline: 1.5033x; 1.0675x over previous
#include <cuda_runtime.h>
#include <cuda_bf16.h>
#include <cstdint>
#include <math.h>

// Router: logits = x @ W^T (N=16384, D=2048, E=64), softmax, top-2, renorm.
// Output fp32 concat: probs [N*64] | indices [N*2] | weights [N*2]
//
// R6: W presplit (hi/lo tf32, permuted) into device globals by a pre-kernel.
// Main GEMM: x rounded to tf32 at STS time (single product pair:
// xt*Wh + xt*Wl = xt*W exactly). 8 warps, 32x32 warp tiles, 16 MMA/ks.
// Ambiguous rows (prob gaps < tau) compacted into a list; refine kernel
// recomputes their candidate logits in exact fp32.

#define D_DIM 2048
#define E_DIM 64
#define BM 128
#define BK 32
#define THREADS 256
#define NCHUNK (D_DIM / BK)   // 64
#define N_ROWS 16384
#define TAU 2e-3f

#define A_STR 36
#define B_STR 40
#define A_FLOATS (BM * A_STR)                       // 4608
#define STAGE_FLOATS (A_FLOATS + 2 * 64 * B_STR)    // 4608 + 5120 = 9728
#define SMEM_BYTES (2 * STAGE_FLOATS * 4)           // 77824

__device__ uint32_t g_Wh[NCHUNK * 64 * 32];   // [chunk][expert][32 permuted]
__device__ uint32_t g_Wl[NCHUNK * 64 * 32];
__device__ int g_count;
__device__ int g_list[N_ROWS];
__device__ int4 g_cand[N_ROWS];

__device__ __forceinline__ uint32_t smem_u32(const void* p) {
    uint32_t a;
    asm("{ .reg .u64 t; cvta.to.shared.u64 t, %1; cvt.u32.u64 %0, t; }" : "=r"(a) : "l"(p));
    return a;
}
__device__ __forceinline__ uint32_t tf32_hi(float x) {
    uint32_t r;
    asm("cvt.rna.tf32.f32 %0, %1;" : "=r"(r) : "f"(x));
    return r;
}
__device__ __forceinline__ void cp_async16(uint32_t dst, const void* src) {
    asm volatile("cp.async.ca.shared.global [%0], [%1], 16;" :: "r"(dst), "l"(src) : "memory");
}
__device__ __forceinline__ void cp_commit() {
    asm volatile("cp.async.commit_group;" ::: "memory");
}
__device__ __forceinline__ void cp_wait1() {
    asm volatile("cp.async.wait_group 1;" ::: "memory");
}
__device__ __forceinline__ void cp_wait0() {
    asm volatile("cp.async.wait_group 0;" ::: "memory");
}
__device__ __forceinline__ void mma_tf32(float* c,
                                         uint32_t a0, uint32_t a1, uint32_t a2, uint32_t a3,
                                         uint32_t b0, uint32_t b1) {
    asm volatile(
        "mma.sync.aligned.m16n8k8.row.col.f32.tf32.tf32.f32 "
        "{%0,%1,%2,%3}, {%4,%5,%6,%7}, {%8,%9}, {%0,%1,%2,%3};"
        : "+f"(c[0]), "+f"(c[1]), "+f"(c[2]), "+f"(c[3])
        : "r"(a0), "r"(a1), "r"(a2), "r"(a3), "r"(b0), "r"(b1));
}

// ---- Pre-kernel: split W into tf32 hi/lo, permuted pair layout ----
// g_W*[chunk][e][ks*8 + 2j + s] = part of W[e][chunk*32 + ks*8 + j + 4s]
__global__ __launch_bounds__(256, 1)
void split_w_kernel(const float* __restrict__ W)
{
    const int g = blockIdx.x * 256 + threadIdx.x;   // 0..16383
    if (g == 0) g_count = 0;
    const int chunk = g >> 8;
    const int r     = g & 255;
    const int e     = r >> 2;
    const int ks    = r & 3;

    const float* src = W + (size_t)e * D_DIM + chunk * 32 + ks * 8;
    float4 f0 = *(const float4*)(src);
    float4 f1 = *(const float4*)(src + 4);

    uint32_t h[8], l[8];
    float v0[8] = {f0.x, f1.x, f0.y, f1.y, f0.z, f1.z, f0.w, f1.w};
#pragma unroll
    for (int i = 0; i < 8; i++) {
        h[i] = tf32_hi(v0[i]);
        l[i] = tf32_hi(v0[i] - __uint_as_float(h[i]));
    }
    uint32_t* dh = g_Wh + ((size_t)chunk * 64 + e) * 32 + ks * 8;
    uint32_t* dl = g_Wl + ((size_t)chunk * 64 + e) * 32 + ks * 8;
    *(uint4*)(dh)     = make_uint4(h[0], h[1], h[2], h[3]);
    *(uint4*)(dh + 4) = make_uint4(h[4], h[5], h[6], h[7]);
    *(uint4*)(dl)     = make_uint4(l[0], l[1], l[2], l[3]);
    *(uint4*)(dl + 4) = make_uint4(l[4], l[5], l[6], l[7]);
}

__global__ __launch_bounds__(THREADS, 1)
void router_kernel(const float* __restrict__ x,
                   float* __restrict__ probs_out,
                   float* __restrict__ idx_out,
                   float* __restrict__ w_out)
{
    extern __shared__ float smem[];

    const int tid  = threadIdx.x;
    const int wid  = tid >> 5;
    const int lane = tid & 31;
    const int m0   = blockIdx.x * BM;

    // 8 warps: 4 row groups x 2 col groups; warp tile 32x32
    const int wr = (wid & 3) * 32;
    const int wc = (wid >> 2) * 32;
    const int qr = lane >> 2;
    const int qc = lane & 3;

    // A loader: thread -> (row = tid>>1, half h = tid&1 -> k offset h*16)
    const int lrow = tid >> 1;
    const int lh   = (tid & 1) * 16;
    const float* xrow = x + (size_t)(m0 + lrow) * D_DIM + lh;

    float acc[2][4][4];
#pragma unroll
    for (int i = 0; i < 2; i++)
#pragma unroll
        for (int j = 0; j < 4; j++)
#pragma unroll
            for (int k = 0; k < 4; k++) acc[i][j][k] = 0.0f;

    auto issue_B = [&](int chunk, int s) {
        float* st = smem + s * STAGE_FLOATS;
        float* Bh = st + A_FLOATS;
        float* Bl = Bh + 64 * B_STR;
#pragma unroll
        for (int i = 0; i < 4; i++) {
            int q    = tid + i * 256;
            int tile = q >> 9;
            int r    = (q >> 3) & 63;
            int seg  = q & 7;
            const uint32_t* src = (tile ? g_Wl : g_Wh)
                                  + ((size_t)chunk * 64 + r) * 32 + seg * 4;
            float* dst = (tile ? Bl : Bh) + r * B_STR + seg * 4;
            cp_async16(smem_u32(dst), src);
        }
        cp_commit();
    };

    // prologue
    issue_B(0, 0);
    float4 af[4];
#pragma unroll
    for (int i = 0; i < 4; i++) af[i] = *(const float4*)(xrow + 4 * i);

    for (int c = 0; c < NCHUNK; c++) {
        const int s = c & 1;
        float* st = smem + s * STAGE_FLOATS;

        if (c + 1 < NCHUNK) issue_B(c + 1, s ^ 1);

        // convert + store A (tf32)
        {
            uint32_t* As = (uint32_t*)st + lrow * A_STR + lh;
#pragma unroll
            for (int i = 0; i < 4; i++) {
                uint4 v = make_uint4(tf32_hi(af[i].x), tf32_hi(af[i].y),
                                     tf32_hi(af[i].z), tf32_hi(af[i].w));
                *(uint4*)(As + 4 * i) = v;
            }
        }

        // prefetch next A chunk
        if (c + 1 < NCHUNK) {
            const float* p = xrow + (c + 1) * BK;
#pragma unroll
            for (int i = 0; i < 4; i++) af[i] = *(const float4*)(p + 4 * i);
        }

        if (c + 1 < NCHUNK) cp_wait1(); else cp_wait0();
        __syncthreads();

        const uint32_t* As = (const uint32_t*)st;
        const uint32_t* Bh = As + A_FLOATS;
        const uint32_t* Bl = Bh + 64 * B_STR;

#pragma unroll
        for (int ks = 0; ks < 4; ks++) {
            const int k0 = ks * 8;

            uint32_t a[2][4];
#pragma unroll
            for (int mt = 0; mt < 2; mt++) {
                const uint32_t* p = As + (wr + mt * 16 + qr) * A_STR + k0 + qc;
                a[mt][0] = p[0];
                a[mt][1] = p[8 * A_STR];
                a[mt][2] = p[4];
                a[mt][3] = p[8 * A_STR + 4];
            }
            uint32_t bh[4][2], bl[4][2];
#pragma unroll
            for (int nt = 0; nt < 4; nt++) {
                const int n = wc + nt * 8 + qr;
                uint2 vh = *(const uint2*)(Bh + n * B_STR + k0 + 2 * qc);
                uint2 vl = *(const uint2*)(Bl + n * B_STR + k0 + 2 * qc);
                bh[nt][0] = vh.x; bh[nt][1] = vh.y;
                bl[nt][0] = vl.x; bl[nt][1] = vl.y;
            }
#pragma unroll
            for (int mt = 0; mt < 2; mt++)
#pragma unroll
                for (int nt = 0; nt < 4; nt++) {
                    mma_tf32(acc[mt][nt], a[mt][0], a[mt][1], a[mt][2], a[mt][3],
                             bh[nt][0], bh[nt][1]);
                    mma_tf32(acc[mt][nt], a[mt][0], a[mt][1], a[mt][2], a[mt][3],
                             bl[nt][0], bl[nt][1]);
                }
        }
        __syncthreads();
    }

    // ---- stage logits into smem overlay ----
    float (*ls)[E_DIM + 2] = (float (*)[E_DIM + 2])smem;
#pragma unroll
    for (int mt = 0; mt < 2; mt++)
#pragma unroll
        for (int nt = 0; nt < 4; nt++) {
            int r  = wr + mt * 16 + qr;
            int cc = wc + nt * 8 + qc * 2;
            ls[r][cc]         = acc[mt][nt][0];
            ls[r][cc + 1]     = acc[mt][nt][1];
            ls[r + 8][cc]     = acc[mt][nt][2];
            ls[r + 8][cc + 1] = acc[mt][nt][3];
        }
    __syncthreads();

    // ---- epilogue: one warp per row (8 warps, 16 rows each) ----
    const unsigned FULL = 0xFFFFFFFFu;

    auto wtop2 = [&](float pa, int ia, float pb, int ib,
                     float& V1, int& I1, float& V2, int& I2) {
        float v1, v2; int i1, i2;
        if (pa >= pb) { v1 = pa; i1 = ia; v2 = pb; i2 = ib; }
        else          { v1 = pb; i1 = ib; v2 = pa; i2 = ia; }
#pragma unroll
        for (int off = 16; off > 0; off >>= 1) {
            float ov1 = __shfl_xor_sync(FULL, v1, off);
            int   oi1 = __shfl_xor_sync(FULL, i1, off);
            float ov2 = __shfl_xor_sync(FULL, v2, off);
            int   oi2 = __shfl_xor_sync(FULL, i2, off);
            bool o_first = (ov1 > v1) || (ov1 == v1 && oi1 < i1);
            float n1, n2; int ni1, ni2;
            if (o_first) {
                n1 = ov1; ni1 = oi1;
                bool aa = (v1 > ov2) || (v1 == ov2 && i1 < oi2);
                if (aa) { n2 = v1;  ni2 = i1;  } else { n2 = ov2; ni2 = oi2; }
            } else {
                n1 = v1; ni1 = i1;
                bool aa = (ov1 > v2) || (ov1 == v2 && oi1 < i2);
                if (aa) { n2 = ov1; ni2 = oi1; } else { n2 = v2;  ni2 = i2;  }
            }
            v1 = n1; i1 = ni1; v2 = n2; i2 = ni2;
        }
        V1 = v1; I1 = i1; V2 = v2; I2 = i2;
    };

    for (int r = wid; r < BM; r += 8) {
        float l1 = ls[r][lane];
        float l2 = ls[r][lane + 32];

        float m = fmaxf(l1, l2);
#pragma unroll
        for (int off = 16; off > 0; off >>= 1)
            m = fmaxf(m, __shfl_xor_sync(FULL, m, off));

        float e1 = expf(l1 - m);
        float e2 = expf(l2 - m);

        float s = e1 + e2;
#pragma unroll
        for (int off = 16; off > 0; off >>= 1)
            s += __shfl_xor_sync(FULL, s, off);
        float inv = 1.0f / s;

        float pa = e1 * inv;
        float pb = e2 * inv;

        const int row = m0 + r;
        probs_out[(size_t)row * E_DIM + lane]      = pa;
        probs_out[(size_t)row * E_DIM + lane + 32] = pb;

        float v1, v2, v3, v4;
        int i1, i2, i3, i4;
        wtop2(pa, lane, pb, lane + 32, v1, i1, v2, i2);

        float pa2 = (lane == i1 || lane == i2) ? -1.0f : pa;
        float pb2 = (lane + 32 == i1 || lane + 32 == i2) ? -1.0f : pb;
        wtop2(pa2, lane, pb2, lane + 32, v3, i3, v4, i4);

        if (lane == 0) {
            float denom = v1 + v2 + 1e-9f;
            idx_out[(size_t)row * 2 + 0] = (float)i1;
            idx_out[(size_t)row * 2 + 1] = (float)i2;
            w_out[(size_t)row * 2 + 0]   = v1 / denom;
            w_out[(size_t)row * 2 + 1]   = v2 / denom;
            if (((v1 - v2) < TAU) || ((v2 - v3) < TAU)) {
                int pos = atomicAdd(&g_count, 1);
                g_list[pos] = row;
                g_cand[pos] = make_int4(i1, i2, i3, i4);
            }
        }
    }
}

// Pass 2: exact fp32 re-evaluation of candidate logits for flagged rows.
__global__ __launch_bounds__(256, 1)
void refine_kernel(const float* __restrict__ x,
                   const float* __restrict__ W,
                   float* __restrict__ idx_out,
                   float* __restrict__ w_out)
{
    const int warp = threadIdx.x >> 5;
    const int lane = threadIdx.x & 31;
    const int cnt  = g_count;
    const int nw   = gridDim.x * 8;

    for (int it = blockIdx.x * 8 + warp; it < cnt; it += nw) {
        const int row = g_list[it];
        const int4 cd = g_cand[it];

        const float* xr = x + (size_t)row * D_DIM;
        const float* w0 = W + (size_t)cd.x * D_DIM;
        const float* w1 = W + (size_t)cd.y * D_DIM;
        const float* w2 = W + (size_t)cd.z * D_DIM;
        const float* w3 = W + (size_t)cd.w * D_DIM;

        float d0 = 0.f, d1 = 0.f, d2 = 0.f, d3 = 0.f;
        for (int k = lane * 4; k < D_DIM; k += 128) {
            float4 xv = *(const float4*)(xr + k);
            float4 a  = *(const float4*)(w0 + k);
            float4 b  = *(const float4*)(w1 + k);
            float4 cc = *(const float4*)(w2 + k);
            float4 dd = *(const float4*)(w3 + k);
            d0 = fmaf(xv.x, a.x,  fmaf(xv.y, a.y,  fmaf(xv.z, a.z,  fmaf(xv.w, a.w,  d0))));
            d1 = fmaf(xv.x, b.x,  fmaf(xv.y, b.y,  fmaf(xv.z, b.z,  fmaf(xv.w, b.w,  d1))));
            d2 = fmaf(xv.x, cc.x, fmaf(xv.y, cc.y, fmaf(xv.z, cc.z, fmaf(xv.w, cc.w, d2))));
            d3 = fmaf(xv.x, dd.x, fmaf(xv.y, dd.y, fmaf(xv.z, dd.z, fmaf(xv.w, dd.w, d3))));
        }
        const unsigned FULL = 0xFFFFFFFFu;
#pragma unroll
        for (int off = 16; off > 0; off >>= 1) {
            d0 += __shfl_xor_sync(FULL, d0, off);
            d1 += __shfl_xor_sync(FULL, d1, off);
            d2 += __shfl_xor_sync(FULL, d2, off);
            d3 += __shfl_xor_sync(FULL, d3, off);
        }

        if (lane == 0) {
            float l[4]  = {d0, d1, d2, d3};
            int   id[4] = {cd.x, cd.y, cd.z, cd.w};
#pragma unroll
            for (int i = 0; i < 2; i++) {
                int best = i;
#pragma unroll
                for (int j = i + 1; j < 4; j++) {
                    if ((l[j] > l[best]) || (l[j] == l[best] && id[j] < id[best])) best = j;
                }
                float tl = l[i]; l[i] = l[best]; l[best] = tl;
                int ti = id[i]; id[i] = id[best]; id[best] = ti;
            }
            float m  = fmaxf(l[0], l[1]);
            float e1 = expf(l[0] - m);
            float e2 = expf(l[1] - m);
            float w1v = e1 / (e1 + e2);
            idx_out[(size_t)row * 2 + 0] = (float)id[0];
            idx_out[(size_t)row * 2 + 1] = (float)id[1];
            w_out[(size_t)row * 2 + 0]   = w1v;
            w_out[(size_t)row * 2 + 1]   = 1.0f - w1v;
        }
    }
}

extern "C" void kernel_launch(void* const* d_in, const int* in_sizes, int n_in,
                              void* d_out, int out_size)
{
    const float* x = (const float*)d_in[0];
    const float* W = (const float*)d_in[1];
    const int N = in_sizes[0] / D_DIM;   // 16384

    float* out   = (float*)d_out;
    float* probs = out;
    float* idx   = out + (size_t)N * E_DIM;
    float* wts   = out + (size_t)N * E_DIM + (size_t)N * 2;

    cudaFuncSetAttribute(router_kernel,
                         cudaFuncAttributeMaxDynamicSharedMemorySize, SMEM_BYTES);

    split_w_kernel<<<64, 256>>>(W);
    router_kernel<<<N / BM, THREADS, SMEM_BYTES>>>(x, probs, idx, wts);
    refine_kernel<<<64, 256>>>(x, W, idx, wts);
}

// round 8
// speedup vs baseline: 1.5791x; 1.0504x over previous
#include <cuda_runtime.h>
#include <cuda_fp16.h>
#include <cstdint>
#include <math.h>

// Router: logits = x @ W^T (N=16384, D=2048, E=64), softmax, top-2, renorm.
// Output fp32 concat: probs [N*64] | indices [N*2] | weights [N*2]
//
// R8: R7 (fp16 m16n8k16, W presplit hi+lo, x rounded to fp16) with the
// misalignment fixed: smem row strides 18 -> 20 u32 so every STS.128 /
// cp.async.16 destination is 16B-aligned. Stride 20 keeps LDS.64 fragment
// reads bank-conflict-free (20*qr mod 32 all distinct for qr 0..7).

#define D_DIM 2048
#define E_DIM 64
#define BM 64
#define BK 32
#define THREADS 256
#define NCHUNK (D_DIM / BK)   // 64
#define N_ROWS 16384
#define TAU 2e-3f

#define A_STR 20                           // u32 stride per row (16 + pad 4)
#define B_STR 20
#define A_U32 (BM * A_STR)                 // 1280
#define STAGE_U32 (A_U32 + 2 * 64 * B_STR) // 1280 + 2560 = 3840
#define SMEM_BYTES (2 * STAGE_U32 * 4)     // 30720

__device__ uint32_t g_Wh[NCHUNK * 64 * 16];   // [chunk][expert][16 u32 permuted fp16x2]
__device__ uint32_t g_Wl[NCHUNK * 64 * 16];
__device__ int g_count;
__device__ int g_list[N_ROWS];
__device__ int4 g_cand[N_ROWS];

__device__ __forceinline__ uint32_t smem_u32(const void* p) {
    uint32_t a;
    asm("{ .reg .u64 t; cvta.to.shared.u64 t, %1; cvt.u32.u64 %0, t; }" : "=r"(a) : "l"(p));
    return a;
}
__device__ __forceinline__ uint32_t h2pack(float lo_k, float hi_k) {
    __half2 h = __floats2half2_rn(lo_k, hi_k);   // .x = low half = even k
    return *(uint32_t*)&h;
}
__device__ __forceinline__ void cp_async16(uint32_t dst, const void* src) {
    asm volatile("cp.async.ca.shared.global [%0], [%1], 16;" :: "r"(dst), "l"(src) : "memory");
}
__device__ __forceinline__ void cp_commit() {
    asm volatile("cp.async.commit_group;" ::: "memory");
}
__device__ __forceinline__ void cp_wait1() {
    asm volatile("cp.async.wait_group 1;" ::: "memory");
}
__device__ __forceinline__ void cp_wait0() {
    asm volatile("cp.async.wait_group 0;" ::: "memory");
}
__device__ __forceinline__ void mma_f16(float* c,
                                        uint32_t a0, uint32_t a1, uint32_t a2, uint32_t a3,
                                        uint32_t b0, uint32_t b1) {
    asm volatile(
        "mma.sync.aligned.m16n8k16.row.col.f32.f16.f16.f32 "
        "{%0,%1,%2,%3}, {%4,%5,%6,%7}, {%8,%9}, {%0,%1,%2,%3};"
        : "+f"(c[0]), "+f"(c[1]), "+f"(c[2]), "+f"(c[3])
        : "r"(a0), "r"(a1), "r"(a2), "r"(a3), "r"(b0), "r"(b1));
}

// ---- Pre-kernel: split W into fp16 hi/lo, permuted fp16x2 pair layout ----
// Slot s (0..15): block b=s>>3, s8=s&7; pl = (s8&1)? (s8>>1)+4 : (s8>>1);
// k = b*16 + 2*pl. LDS.64 at slot 2*qc then yields k-pairs {2qc, 2qc+8}.
__global__ __launch_bounds__(256, 1)
void split_w_kernel(const float* __restrict__ W)
{
    const int g = blockIdx.x * 256 + threadIdx.x;   // 0..4095
    if (g == 0) g_count = 0;
    if (g >= NCHUNK * 64) return;
    const int chunk = g >> 6;
    const int e     = g & 63;

    const float* src = W + (size_t)e * D_DIM + chunk * 32;
    float v[32];
#pragma unroll
    for (int i = 0; i < 8; i++) {
        float4 f = *(const float4*)(src + 4 * i);
        v[4 * i] = f.x; v[4 * i + 1] = f.y; v[4 * i + 2] = f.z; v[4 * i + 3] = f.w;
    }

    uint32_t* dh = g_Wh + ((size_t)chunk * 64 + e) * 16;
    uint32_t* dl = g_Wl + ((size_t)chunk * 64 + e) * 16;
#pragma unroll
    for (int s = 0; s < 16; s++) {
        int b  = s >> 3;
        int s8 = s & 7;
        int pl = (s8 & 1) ? ((s8 >> 1) + 4) : (s8 >> 1);
        int k  = b * 16 + 2 * pl;
        __half2 h = __floats2half2_rn(v[k], v[k + 1]);
        dh[s] = *(uint32_t*)&h;
        float l0 = v[k]     - __low2float(h);
        float l1 = v[k + 1] - __high2float(h);
        __half2 l = __floats2half2_rn(l0, l1);
        dl[s] = *(uint32_t*)&l;
    }
}

__global__ __launch_bounds__(THREADS, 1)
void router_kernel(const float* __restrict__ x,
                   float* __restrict__ probs_out,
                   float* __restrict__ idx_out,
                   float* __restrict__ w_out)
{
    extern __shared__ uint32_t smem[];

    const int tid  = threadIdx.x;
    const int wid  = tid >> 5;
    const int lane = tid & 31;
    const int m0   = blockIdx.x * BM;

    // 8 warps: 2 row groups x 4 col groups; warp tile 32x16
    const int wr = (wid & 1) * 32;
    const int wc = (wid >> 1) * 16;
    const int qr = lane >> 2;   // 0..7
    const int qc = lane & 3;    // 0..3

    // A loader: thread -> (row = tid>>2, quarter q = tid&3)
    const int lrow = tid >> 2;
    const int lq   = tid & 3;
    const int lk0  = (lq & 1) * 4 + (lq >> 1) * 16;
    const float* xrow = x + (size_t)(m0 + lrow) * D_DIM + lk0;

    float accM[2][2][4];
#pragma unroll
    for (int i = 0; i < 2; i++)
#pragma unroll
        for (int j = 0; j < 2; j++)
#pragma unroll
            for (int k = 0; k < 4; k++) accM[i][j][k] = 0.0f;

    auto issue_B = [&](int chunk, int s) {
        uint32_t* Bbase = smem + s * STAGE_U32 + A_U32;
#pragma unroll
        for (int i = 0; i < 2; i++) {
            int idx  = tid + i * 256;           // 0..511
            int term = idx >> 8;                // 0=hi, 1=lo
            int r    = (idx >> 2) & 63;
            int seg  = idx & 3;
            const uint32_t* src = (term ? g_Wl : g_Wh)
                                  + ((size_t)chunk * 64 + r) * 16 + seg * 4;
            uint32_t* dst = Bbase + term * 64 * B_STR + r * B_STR + seg * 4;
            cp_async16(smem_u32(dst), src);
        }
        cp_commit();
    };

    // prologue
    issue_B(0, 0);
    float4 af0 = *(const float4*)(xrow);
    float4 af1 = *(const float4*)(xrow + 8);

    for (int c = 0; c < NCHUNK; c++) {
        const int s = c & 1;
        uint32_t* st = smem + s * STAGE_U32;

        if (c + 1 < NCHUNK) issue_B(c + 1, s ^ 1);

        // convert + store A (fp16, permuted pair layout), 1 STS.128
        {
            uint4 v;
            v.x = h2pack(af0.x, af0.y);   // k pair lk0
            v.y = h2pack(af1.x, af1.y);   // k pair lk0+8
            v.z = h2pack(af0.z, af0.w);   // k pair lk0+2
            v.w = h2pack(af1.z, af1.w);   // k pair lk0+10
            *(uint4*)(st + lrow * A_STR + lq * 4) = v;
        }

        // prefetch next A chunk
        if (c + 1 < NCHUNK) {
            const float* p = xrow + (c + 1) * BK;
            af0 = *(const float4*)(p);
            af1 = *(const float4*)(p + 8);
        }

        if (c + 1 < NCHUNK) cp_wait1(); else cp_wait0();
        __syncthreads();

        const uint32_t* As = st;
        const uint32_t* Bh = st + A_U32;
        const uint32_t* Bl = Bh + 64 * B_STR;

        float accL[2][2][4];
#pragma unroll
        for (int i = 0; i < 2; i++)
#pragma unroll
            for (int j = 0; j < 2; j++)
#pragma unroll
                for (int k = 0; k < 4; k++) accL[i][j][k] = 0.0f;

#pragma unroll
        for (int ksb = 0; ksb < 2; ksb++) {
            const int so = ksb * 8 + 2 * qc;

            uint32_t a[2][4];
#pragma unroll
            for (int mt = 0; mt < 2; mt++) {
                const int r0 = wr + mt * 16 + qr;
                uint2 lo = *(const uint2*)(As + r0 * A_STR + so);
                uint2 hi = *(const uint2*)(As + (r0 + 8) * A_STR + so);
                a[mt][0] = lo.x; a[mt][2] = lo.y;
                a[mt][1] = hi.x; a[mt][3] = hi.y;
            }
            uint2 bh[2], bl[2];
#pragma unroll
            for (int nt = 0; nt < 2; nt++) {
                const int n = wc + nt * 8 + qr;
                bh[nt] = *(const uint2*)(Bh + n * B_STR + so);
                bl[nt] = *(const uint2*)(Bl + n * B_STR + so);
            }
#pragma unroll
            for (int mt = 0; mt < 2; mt++)
#pragma unroll
                for (int nt = 0; nt < 2; nt++) {
                    mma_f16(accL[mt][nt], a[mt][0], a[mt][1], a[mt][2], a[mt][3],
                            bh[nt].x, bh[nt].y);
                    mma_f16(accL[mt][nt], a[mt][0], a[mt][1], a[mt][2], a[mt][3],
                            bl[nt].x, bl[nt].y);
                }
        }

        // fold (IEEE RN) to contain truncation bias
#pragma unroll
        for (int i = 0; i < 2; i++)
#pragma unroll
            for (int j = 0; j < 2; j++)
#pragma unroll
                for (int k = 0; k < 4; k++) accM[i][j][k] += accL[i][j][k];

        __syncthreads();
    }

    // ---- stage logits into smem overlay ----
    float (*ls)[E_DIM + 2] = (float (*)[E_DIM + 2])smem;
#pragma unroll
    for (int mt = 0; mt < 2; mt++)
#pragma unroll
        for (int nt = 0; nt < 2; nt++) {
            int r  = wr + mt * 16 + qr;
            int cc = wc + nt * 8 + qc * 2;
            ls[r][cc]         = accM[mt][nt][0];
            ls[r][cc + 1]     = accM[mt][nt][1];
            ls[r + 8][cc]     = accM[mt][nt][2];
            ls[r + 8][cc + 1] = accM[mt][nt][3];
        }
    __syncthreads();

    // ---- epilogue: one warp per row (8 warps, 64 rows -> 8 each) ----
    const unsigned FULL = 0xFFFFFFFFu;

    auto wtop2 = [&](float pa, int ia, float pb, int ib,
                     float& V1, int& I1, float& V2, int& I2) {
        float v1, v2; int i1, i2;
        if (pa >= pb) { v1 = pa; i1 = ia; v2 = pb; i2 = ib; }
        else          { v1 = pb; i1 = ib; v2 = pa; i2 = ia; }
#pragma unroll
        for (int off = 16; off > 0; off >>= 1) {
            float ov1 = __shfl_xor_sync(FULL, v1, off);
            int   oi1 = __shfl_xor_sync(FULL, i1, off);
            float ov2 = __shfl_xor_sync(FULL, v2, off);
            int   oi2 = __shfl_xor_sync(FULL, i2, off);
            bool o_first = (ov1 > v1) || (ov1 == v1 && oi1 < i1);
            float n1, n2; int ni1, ni2;
            if (o_first) {
                n1 = ov1; ni1 = oi1;
                bool aa = (v1 > ov2) || (v1 == ov2 && i1 < oi2);
                if (aa) { n2 = v1;  ni2 = i1;  } else { n2 = ov2; ni2 = oi2; }
            } else {
                n1 = v1; ni1 = i1;
                bool aa = (ov1 > v2) || (ov1 == v2 && oi1 < i2);
                if (aa) { n2 = ov1; ni2 = oi1; } else { n2 = v2;  ni2 = i2;  }
            }
            v1 = n1; i1 = ni1; v2 = n2; i2 = ni2;
        }
        V1 = v1; I1 = i1; V2 = v2; I2 = i2;
    };

    for (int r = wid; r < BM; r += 8) {
        float l1 = ls[r][lane];
        float l2 = ls[r][lane + 32];

        float m = fmaxf(l1, l2);
#pragma unroll
        for (int off = 16; off > 0; off >>= 1)
            m = fmaxf(m, __shfl_xor_sync(FULL, m, off));

        float e1 = expf(l1 - m);
        float e2 = expf(l2 - m);

        float s = e1 + e2;
#pragma unroll
        for (int off = 16; off > 0; off >>= 1)
            s += __shfl_xor_sync(FULL, s, off);
        float inv = 1.0f / s;

        float pa = e1 * inv;
        float pb = e2 * inv;

        const int row = m0 + r;
        probs_out[(size_t)row * E_DIM + lane]      = pa;
        probs_out[(size_t)row * E_DIM + lane + 32] = pb;

        float v1, v2, v3, v4;
        int i1, i2, i3, i4;
        wtop2(pa, lane, pb, lane + 32, v1, i1, v2, i2);

        float pa2 = (lane == i1 || lane == i2) ? -1.0f : pa;
        float pb2 = (lane + 32 == i1 || lane + 32 == i2) ? -1.0f : pb;
        wtop2(pa2, lane, pb2, lane + 32, v3, i3, v4, i4);

        if (lane == 0) {
            float denom = v1 + v2 + 1e-9f;
            idx_out[(size_t)row * 2 + 0] = (float)i1;
            idx_out[(size_t)row * 2 + 1] = (float)i2;
            w_out[(size_t)row * 2 + 0]   = v1 / denom;
            w_out[(size_t)row * 2 + 1]   = v2 / denom;
            if (((v1 - v2) < TAU) || ((v2 - v3) < TAU)) {
                int pos = atomicAdd(&g_count, 1);
                g_list[pos] = row;
                g_cand[pos] = make_int4(i1, i2, i3, i4);
            }
        }
    }
}

// Pass 2: exact fp32 re-evaluation of candidate logits for flagged rows.
__global__ __launch_bounds__(256, 1)
void refine_kernel(const float* __restrict__ x,
                   const float* __restrict__ W,
                   float* __restrict__ idx_out,
                   float* __restrict__ w_out)
{
    const int warp = threadIdx.x >> 5;
    const int lane = threadIdx.x & 31;
    const int cnt  = g_count;
    const int nw   = gridDim.x * 8;

    for (int it = blockIdx.x * 8 + warp; it < cnt; it += nw) {
        const int row = g_list[it];
        const int4 cd = g_cand[it];

        const float* xr = x + (size_t)row * D_DIM;
        const float* w0 = W + (size_t)cd.x * D_DIM;
        const float* w1 = W + (size_t)cd.y * D_DIM;
        const float* w2 = W + (size_t)cd.z * D_DIM;
        const float* w3 = W + (size_t)cd.w * D_DIM;

        float d0 = 0.f, d1 = 0.f, d2 = 0.f, d3 = 0.f;
        for (int k = lane * 4; k < D_DIM; k += 128) {
            float4 xv = *(const float4*)(xr + k);
            float4 a  = *(const float4*)(w0 + k);
            float4 b  = *(const float4*)(w1 + k);
            float4 cc = *(const float4*)(w2 + k);
            float4 dd = *(const float4*)(w3 + k);
            d0 = fmaf(xv.x, a.x,  fmaf(xv.y, a.y,  fmaf(xv.z, a.z,  fmaf(xv.w, a.w,  d0))));
            d1 = fmaf(xv.x, b.x,  fmaf(xv.y, b.y,  fmaf(xv.z, b.z,  fmaf(xv.w, b.w,  d1))));
            d2 = fmaf(xv.x, cc.x, fmaf(xv.y, cc.y, fmaf(xv.z, cc.z, fmaf(xv.w, cc.w, d2))));
            d3 = fmaf(xv.x, dd.x, fmaf(xv.y, dd.y, fmaf(xv.z, dd.z, fmaf(xv.w, dd.w, d3))));
        }
        const unsigned FULL = 0xFFFFFFFFu;
#pragma unroll
        for (int off = 16; off > 0; off >>= 1) {
            d0 += __shfl_xor_sync(FULL, d0, off);
            d1 += __shfl_xor_sync(FULL, d1, off);
            d2 += __shfl_xor_sync(FULL, d2, off);
            d3 += __shfl_xor_sync(FULL, d3, off);
        }

        if (lane == 0) {
            float l[4]  = {d0, d1, d2, d3};
            int   id[4] = {cd.x, cd.y, cd.z, cd.w};
#pragma unroll
            for (int i = 0; i < 2; i++) {
                int best = i;
#pragma unroll
                for (int j = i + 1; j < 4; j++) {
                    if ((l[j] > l[best]) || (l[j] == l[best] && id[j] < id[best])) best = j;
                }
                float tl = l[i]; l[i] = l[best]; l[best] = tl;
                int ti = id[i]; id[i] = id[best]; id[best] = ti;
            }
            float m  = fmaxf(l[0], l[1]);
            float e1 = expf(l[0] - m);
            float e2 = expf(l[1] - m);
            float w1v = e1 / (e1 + e2);
            idx_out[(size_t)row * 2 + 0] = (float)id[0];
            idx_out[(size_t)row * 2 + 1] = (float)id[1];
            w_out[(size_t)row * 2 + 0]   = w1v;
            w_out[(size_t)row * 2 + 1]   = 1.0f - w1v;
        }
    }
}

extern "C" void kernel_launch(void* const* d_in, const int* in_sizes, int n_in,
                              void* d_out, int out_size)
{
    const float* x = (const float*)d_in[0];
    const float* W = (const float*)d_in[1];
    const int N = in_sizes[0] / D_DIM;   // 16384

    float* out   = (float*)d_out;
    float* probs = out;
    float* idx   = out + (size_t)N * E_DIM;
    float* wts   = out + (size_t)N * E_DIM + (size_t)N * 2;

    split_w_kernel<<<16, 256>>>(W);
    router_kernel<<<N / BM, THREADS, SMEM_BYTES>>>(x, probs, idx, wts);
    refine_kernel<<<64, 256>>>(x, W, idx, wts);
}

// round 9
// speedup vs baseline: 1.6177x; 1.0244x over previous
#include <cuda_runtime.h>
#include <cuda_fp16.h>
#include <cstdint>
#include <math.h>

// Router: logits = x @ W^T (N=16384, D=2048, E=64), softmax, top-2, renorm.
// Output fp32 concat: probs [N*64] | indices [N*2] | weights [N*2]
//
// R9: loads moved off the LSU. x tiles arrive via cp.async.bulk (64 row-bulks
// of 256B per chunk) into fp32 smem; W is pre-split/permuted per chunk into
// one contiguous block (g_B) and fetched with a single 18KB bulk per chunk.
// mbarrier(expect_tx) 2-stage pipeline. In-CTA convert packs x fp32 -> fp16
// permuted tile (R8-validated layout); fp16 m16n8k16 MMA, W hi+lo terms,
// chunk-local accumulator fold; ambiguous rows refined exactly in pass 2.

#define D_DIM 2048
#define E_DIM 64
#define BM 64
#define BK 64
#define THREADS 256
#define NCHUNK (D_DIM / BK)   // 32
#define N_ROWS 16384
#define TAU 2e-3f

// smem byte offsets
#define SM_MBAR 0                                  // 2 x 8B mbarriers
#define SM_BASE 128
#define A32_STR 68                                 // floats per row (64 + pad)
#define A32_BYTES (BM * A32_STR * 4)               // 17408
#define B_STR 36                                   // u32 per expert row (32 + pad)
#define B_BYTES (2 * 64 * B_STR * 4)               // 18432
#define STAGE_BYTES (A32_BYTES + B_BYTES)          // 35840
#define A16_STR 36                                 // u32 per row (32 + pad)
#define SM_A16 (SM_BASE + 2 * STAGE_BYTES)         // 71808
#define A16_BYTES (BM * A16_STR * 4)               // 9216
#define SMEM_BYTES (SM_A16 + A16_BYTES)            // 81024
#define TX_BYTES (BM * BK * 4 + B_BYTES)           // 16384 + 18432 = 34816

// g_B[chunk][term][expert][B_STR u32] : permuted fp16x2 slots, smem-identical
__device__ uint32_t g_B[NCHUNK * 2 * 64 * B_STR];
__device__ int g_count;
__device__ int g_list[N_ROWS];
__device__ int4 g_cand[N_ROWS];

__device__ __forceinline__ uint32_t smem_u32(const void* p) {
    uint32_t a;
    asm("{ .reg .u64 t; cvta.to.shared.u64 t, %1; cvt.u32.u64 %0, t; }" : "=r"(a) : "l"(p));
    return a;
}
__device__ __forceinline__ uint32_t h2pack(float a, float b) {
    __half2 h = __floats2half2_rn(a, b);
    return *(uint32_t*)&h;
}
__device__ __forceinline__ void mma_f16(float* c,
                                        uint32_t a0, uint32_t a1, uint32_t a2, uint32_t a3,
                                        uint32_t b0, uint32_t b1) {
    asm volatile(
        "mma.sync.aligned.m16n8k16.row.col.f32.f16.f16.f32 "
        "{%0,%1,%2,%3}, {%4,%5,%6,%7}, {%8,%9}, {%0,%1,%2,%3};"
        : "+f"(c[0]), "+f"(c[1]), "+f"(c[2]), "+f"(c[3])
        : "r"(a0), "r"(a1), "r"(a2), "r"(a3), "r"(b0), "r"(b1));
}
__device__ __forceinline__ void mbar_init(uint32_t m, uint32_t cnt) {
    asm volatile("mbarrier.init.shared.b64 [%0], %1;" :: "r"(m), "r"(cnt) : "memory");
}
__device__ __forceinline__ void mbar_expect(uint32_t m, uint32_t tx) {
    asm volatile("mbarrier.arrive.expect_tx.shared.b64 _, [%0], %1;" :: "r"(m), "r"(tx) : "memory");
}
__device__ __forceinline__ void bulk_g2s(uint32_t dst, const void* src, uint32_t bytes, uint32_t mbar) {
    asm volatile(
        "cp.async.bulk.shared::cluster.global.mbarrier::complete_tx::bytes [%0], [%1], %2, [%3];"
        :: "r"(dst), "l"(src), "r"(bytes), "r"(mbar) : "memory");
}
__device__ __forceinline__ void mbar_wait(uint32_t m, uint32_t parity) {
    uint32_t done;
    asm volatile(
        "{\n\t.reg .pred p;\n\t"
        "mbarrier.try_wait.parity.acquire.cta.shared::cta.b64 p, [%1], %2;\n\t"
        "selp.b32 %0, 1, 0, p;\n\t}"
        : "=r"(done) : "r"(m), "r"(parity) : "memory");
    if (!done) {
        asm volatile(
            "{\n\t.reg .pred P1;\n\t"
            "W_%=:\n\t"
            "mbarrier.try_wait.parity.acquire.cta.shared::cta.b64 P1, [%0], %1, 0x989680;\n\t"
            "@P1 bra.uni DN_%=;\n\t"
            "bra.uni W_%=;\n\t"
            "DN_%=:\n\t}"
            :: "r"(m), "r"(parity) : "memory");
    }
}

// ---- Pre-kernel: build g_B (fp16 hi/lo, permuted slots, padded rows) ----
// slot s within a 32-k sub-chunk: b=s>>3, s8=s&7, pl=(s8&1)?((s8>>1)+4):(s8>>1),
// k = 32*sub + b*16 + 2*pl. (Layout validated in R8.)
__global__ __launch_bounds__(256, 1)
void split_w_kernel(const float* __restrict__ W)
{
    const int g = blockIdx.x * 256 + threadIdx.x;   // 0..2047
    if (g == 0) g_count = 0;
    if (g >= NCHUNK * 64) return;
    const int chunk = g >> 6;
    const int e     = g & 63;

    const float* src = W + (size_t)e * D_DIM + chunk * BK;
    float v[64];
#pragma unroll
    for (int i = 0; i < 16; i++) {
        float4 f = *(const float4*)(src + 4 * i);
        v[4 * i] = f.x; v[4 * i + 1] = f.y; v[4 * i + 2] = f.z; v[4 * i + 3] = f.w;
    }

    uint32_t hi[32], lo[32];
#pragma unroll
    for (int sub = 0; sub < 2; sub++) {
#pragma unroll
        for (int s = 0; s < 16; s++) {
            int b  = s >> 3;
            int s8 = s & 7;
            int pl = (s8 & 1) ? ((s8 >> 1) + 4) : (s8 >> 1);
            int k  = 32 * sub + b * 16 + 2 * pl;
            __half2 h = __floats2half2_rn(v[k], v[k + 1]);
            hi[sub * 16 + s] = *(uint32_t*)&h;
            float l0 = v[k]     - __low2float(h);
            float l1 = v[k + 1] - __high2float(h);
            __half2 l = __floats2half2_rn(l0, l1);
            lo[sub * 16 + s] = *(uint32_t*)&l;
        }
    }
    uint32_t* dh = g_B + (((size_t)chunk * 2 + 0) * 64 + e) * B_STR;
    uint32_t* dl = g_B + (((size_t)chunk * 2 + 1) * 64 + e) * B_STR;
#pragma unroll
    for (int i = 0; i < 8; i++) {
        *(uint4*)(dh + 4 * i) = *(uint4*)(hi + 4 * i);
        *(uint4*)(dl + 4 * i) = *(uint4*)(lo + 4 * i);
    }
}

__global__ __launch_bounds__(THREADS, 1)
void router_kernel(const float* __restrict__ x,
                   float* __restrict__ probs_out,
                   float* __restrict__ idx_out,
                   float* __restrict__ w_out)
{
    extern __shared__ char smem[];
    const uint32_t sbase = smem_u32(smem);

    const int tid  = threadIdx.x;
    const int wid  = tid >> 5;
    const int lane = tid & 31;
    const int m0   = blockIdx.x * BM;

    // 8 warps: 2 row groups x 4 col groups; warp tile 32x16
    const int wr = (wid & 1) * 32;
    const int wc = (wid >> 1) * 16;
    const int qr = lane >> 2;   // 0..7
    const int qc = lane & 3;    // 0..3

    // converter mapping: thread -> (row = tid>>2, lq = tid&3)
    const int crow = tid >> 2;
    const int clq  = tid & 3;
    const int ck0  = (clq & 1) * 4 + (clq >> 1) * 16;   // within 32-k sub-chunk

    if (tid == 0) {
        mbar_init(sbase + SM_MBAR + 0, 1);
        mbar_init(sbase + SM_MBAR + 8, 1);
    }
    __syncthreads();

    auto issue = [&](int chunk) {
        const int s = chunk & 1;
        const uint32_t a32 = sbase + SM_BASE + s * STAGE_BYTES;
        const uint32_t bsm = a32 + A32_BYTES;
        const uint32_t mb  = sbase + SM_MBAR + s * 8;
        if (tid == 0) {
            mbar_expect(mb, TX_BYTES);
            bulk_g2s(bsm, g_B + (size_t)chunk * 2 * 64 * B_STR, B_BYTES, mb);
        }
        if (tid < BM) {
            const float* src = x + (size_t)(m0 + tid) * D_DIM + chunk * BK;
            bulk_g2s(a32 + tid * (A32_STR * 4), src, BK * 4, mb);
        }
    };

    float accM[2][2][4];
#pragma unroll
    for (int i = 0; i < 2; i++)
#pragma unroll
        for (int j = 0; j < 2; j++)
#pragma unroll
            for (int k = 0; k < 4; k++) accM[i][j][k] = 0.0f;

    issue(0);

    uint32_t* const A16 = (uint32_t*)(smem + SM_A16);

    for (int c = 0; c < NCHUNK; c++) {
        const int s = c & 1;
        if (c + 1 < NCHUNK) issue(c + 1);

        mbar_wait(sbase + SM_MBAR + s * 8, (c >> 1) & 1);

        const float*    A32 = (const float*)(smem + SM_BASE + s * STAGE_BYTES);
        const uint32_t* Bh  = (const uint32_t*)(smem + SM_BASE + s * STAGE_BYTES + A32_BYTES);
        const uint32_t* Bl  = Bh + 64 * B_STR;

        // convert fp32 -> fp16 permuted tile (R8 packing), 2 sub-chunks
#pragma unroll
        for (int sub = 0; sub < 2; sub++) {
            const float* p = A32 + crow * A32_STR + 32 * sub + ck0;
            float4 f0 = *(const float4*)(p);
            float4 f1 = *(const float4*)(p + 8);
            uint4 v;
            v.x = h2pack(f0.x, f0.y);
            v.y = h2pack(f1.x, f1.y);
            v.z = h2pack(f0.z, f0.w);
            v.w = h2pack(f1.z, f1.w);
            *(uint4*)(A16 + crow * A16_STR + sub * 16 + clq * 4) = v;
        }
        __syncthreads();

        float accL[2][2][4];
#pragma unroll
        for (int i = 0; i < 2; i++)
#pragma unroll
            for (int j = 0; j < 2; j++)
#pragma unroll
                for (int k = 0; k < 4; k++) accL[i][j][k] = 0.0f;

#pragma unroll
        for (int K = 0; K < 4; K++) {
            const int so = (K >> 1) * 16 + (K & 1) * 8 + 2 * qc;

            uint32_t a[2][4];
#pragma unroll
            for (int mt = 0; mt < 2; mt++) {
                const int r0 = wr + mt * 16 + qr;
                uint2 lo2 = *(const uint2*)(A16 + r0 * A16_STR + so);
                uint2 hi2 = *(const uint2*)(A16 + (r0 + 8) * A16_STR + so);
                a[mt][0] = lo2.x; a[mt][2] = lo2.y;
                a[mt][1] = hi2.x; a[mt][3] = hi2.y;
            }
            uint2 bh[2], bl[2];
#pragma unroll
            for (int nt = 0; nt < 2; nt++) {
                const int n = wc + nt * 8 + qr;
                bh[nt] = *(const uint2*)(Bh + n * B_STR + so);
                bl[nt] = *(const uint2*)(Bl + n * B_STR + so);
            }
#pragma unroll
            for (int mt = 0; mt < 2; mt++)
#pragma unroll
                for (int nt = 0; nt < 2; nt++) {
                    mma_f16(accL[mt][nt], a[mt][0], a[mt][1], a[mt][2], a[mt][3],
                            bh[nt].x, bh[nt].y);
                    mma_f16(accL[mt][nt], a[mt][0], a[mt][1], a[mt][2], a[mt][3],
                            bl[nt].x, bl[nt].y);
                }
        }

#pragma unroll
        for (int i = 0; i < 2; i++)
#pragma unroll
            for (int j = 0; j < 2; j++)
#pragma unroll
                for (int k = 0; k < 4; k++) accM[i][j][k] += accL[i][j][k];

        __syncthreads();
    }

    // ---- stage logits into smem overlay ----
    float (*ls)[E_DIM + 2] = (float (*)[E_DIM + 2])smem;
#pragma unroll
    for (int mt = 0; mt < 2; mt++)
#pragma unroll
        for (int nt = 0; nt < 2; nt++) {
            int r  = wr + mt * 16 + qr;
            int cc = wc + nt * 8 + qc * 2;
            ls[r][cc]         = accM[mt][nt][0];
            ls[r][cc + 1]     = accM[mt][nt][1];
            ls[r + 8][cc]     = accM[mt][nt][2];
            ls[r + 8][cc + 1] = accM[mt][nt][3];
        }
    __syncthreads();

    // ---- epilogue: one warp per row (8 warps, 64 rows -> 8 each) ----
    const unsigned FULL = 0xFFFFFFFFu;

    auto wtop2 = [&](float pa, int ia, float pb, int ib,
                     float& V1, int& I1, float& V2, int& I2) {
        float v1, v2; int i1, i2;
        if (pa >= pb) { v1 = pa; i1 = ia; v2 = pb; i2 = ib; }
        else          { v1 = pb; i1 = ib; v2 = pa; i2 = ia; }
#pragma unroll
        for (int off = 16; off > 0; off >>= 1) {
            float ov1 = __shfl_xor_sync(FULL, v1, off);
            int   oi1 = __shfl_xor_sync(FULL, i1, off);
            float ov2 = __shfl_xor_sync(FULL, v2, off);
            int   oi2 = __shfl_xor_sync(FULL, i2, off);
            bool o_first = (ov1 > v1) || (ov1 == v1 && oi1 < i1);
            float n1, n2; int ni1, ni2;
            if (o_first) {
                n1 = ov1; ni1 = oi1;
                bool aa = (v1 > ov2) || (v1 == ov2 && i1 < oi2);
                if (aa) { n2 = v1;  ni2 = i1;  } else { n2 = ov2; ni2 = oi2; }
            } else {
                n1 = v1; ni1 = i1;
                bool aa = (ov1 > v2) || (ov1 == v2 && oi1 < i2);
                if (aa) { n2 = ov1; ni2 = oi1; } else { n2 = v2;  ni2 = i2;  }
            }
            v1 = n1; i1 = ni1; v2 = n2; i2 = ni2;
        }
        V1 = v1; I1 = i1; V2 = v2; I2 = i2;
    };

    for (int r = wid; r < BM; r += 8) {
        float l1 = ls[r][lane];
        float l2 = ls[r][lane + 32];

        float m = fmaxf(l1, l2);
#pragma unroll
        for (int off = 16; off > 0; off >>= 1)
            m = fmaxf(m, __shfl_xor_sync(FULL, m, off));

        float e1 = expf(l1 - m);
        float e2 = expf(l2 - m);

        float s = e1 + e2;
#pragma unroll
        for (int off = 16; off > 0; off >>= 1)
            s += __shfl_xor_sync(FULL, s, off);
        float inv = 1.0f / s;

        float pa = e1 * inv;
        float pb = e2 * inv;

        const int row = m0 + r;
        probs_out[(size_t)row * E_DIM + lane]      = pa;
        probs_out[(size_t)row * E_DIM + lane + 32] = pb;

        float v1, v2, v3, v4;
        int i1, i2, i3, i4;
        wtop2(pa, lane, pb, lane + 32, v1, i1, v2, i2);

        float pa2 = (lane == i1 || lane == i2) ? -1.0f : pa;
        float pb2 = (lane + 32 == i1 || lane + 32 == i2) ? -1.0f : pb;
        wtop2(pa2, lane, pb2, lane + 32, v3, i3, v4, i4);

        if (lane == 0) {
            float denom = v1 + v2 + 1e-9f;
            idx_out[(size_t)row * 2 + 0] = (float)i1;
            idx_out[(size_t)row * 2 + 1] = (float)i2;
            w_out[(size_t)row * 2 + 0]   = v1 / denom;
            w_out[(size_t)row * 2 + 1]   = v2 / denom;
            if (((v1 - v2) < TAU) || ((v2 - v3) < TAU)) {
                int pos = atomicAdd(&g_count, 1);
                g_list[pos] = row;
                g_cand[pos] = make_int4(i1, i2, i3, i4);
            }
        }
    }
}

// Pass 2: exact fp32 re-evaluation of candidate logits for flagged rows.
__global__ __launch_bounds__(256, 1)
void refine_kernel(const float* __restrict__ x,
                   const float* __restrict__ W,
                   float* __restrict__ idx_out,
                   float* __restrict__ w_out)
{
    const int warp = threadIdx.x >> 5;
    const int lane = threadIdx.x & 31;
    const int cnt  = g_count;
    const int nw   = gridDim.x * 8;

    for (int it = blockIdx.x * 8 + warp; it < cnt; it += nw) {
        const int row = g_list[it];
        const int4 cd = g_cand[it];

        const float* xr = x + (size_t)row * D_DIM;
        const float* w0 = W + (size_t)cd.x * D_DIM;
        const float* w1 = W + (size_t)cd.y * D_DIM;
        const float* w2 = W + (size_t)cd.z * D_DIM;
        const float* w3 = W + (size_t)cd.w * D_DIM;

        float d0 = 0.f, d1 = 0.f, d2 = 0.f, d3 = 0.f;
        for (int k = lane * 4; k < D_DIM; k += 128) {
            float4 xv = *(const float4*)(xr + k);
            float4 a  = *(const float4*)(w0 + k);
            float4 b  = *(const float4*)(w1 + k);
            float4 cc = *(const float4*)(w2 + k);
            float4 dd = *(const float4*)(w3 + k);
            d0 = fmaf(xv.x, a.x,  fmaf(xv.y, a.y,  fmaf(xv.z, a.z,  fmaf(xv.w, a.w,  d0))));
            d1 = fmaf(xv.x, b.x,  fmaf(xv.y, b.y,  fmaf(xv.z, b.z,  fmaf(xv.w, b.w,  d1))));
            d2 = fmaf(xv.x, cc.x, fmaf(xv.y, cc.y, fmaf(xv.z, cc.z, fmaf(xv.w, cc.w, d2))));
            d3 = fmaf(xv.x, dd.x, fmaf(xv.y, dd.y, fmaf(xv.z, dd.z, fmaf(xv.w, dd.w, d3))));
        }
        const unsigned FULL = 0xFFFFFFFFu;
#pragma unroll
        for (int off = 16; off > 0; off >>= 1) {
            d0 += __shfl_xor_sync(FULL, d0, off);
            d1 += __shfl_xor_sync(FULL, d1, off);
            d2 += __shfl_xor_sync(FULL, d2, off);
            d3 += __shfl_xor_sync(FULL, d3, off);
        }

        if (lane == 0) {
            float l[4]  = {d0, d1, d2, d3};
            int   id[4] = {cd.x, cd.y, cd.z, cd.w};
#pragma unroll
            for (int i = 0; i < 2; i++) {
                int best = i;
#pragma unroll
                for (int j = i + 1; j < 4; j++) {
                    if ((l[j] > l[best]) || (l[j] == l[best] && id[j] < id[best])) best = j;
                }
                float tl = l[i]; l[i] = l[best]; l[best] = tl;
                int ti = id[i]; id[i] = id[best]; id[best] = ti;
            }
            float m  = fmaxf(l[0], l[1]);
            float e1 = expf(l[0] - m);
            float e2 = expf(l[1] - m);
            float w1v = e1 / (e1 + e2);
            idx_out[(size_t)row * 2 + 0] = (float)id[0];
            idx_out[(size_t)row * 2 + 1] = (float)id[1];
            w_out[(size_t)row * 2 + 0]   = w1v;
            w_out[(size_t)row * 2 + 1]   = 1.0f - w1v;
        }
    }
}

extern "C" void kernel_launch(void* const* d_in, const int* in_sizes, int n_in,
                              void* d_out, int out_size)
{
    const float* x = (const float*)d_in[0];
    const float* W = (const float*)d_in[1];
    const int N = in_sizes[0] / D_DIM;   // 16384

    float* out   = (float*)d_out;
    float* probs = out;
    float* idx   = out + (size_t)N * E_DIM;
    float* wts   = out + (size_t)N * E_DIM + (size_t)N * 2;

    cudaFuncSetAttribute(router_kernel,
                         cudaFuncAttributeMaxDynamicSharedMemorySize, SMEM_BYTES);

    split_w_kernel<<<8, 256>>>(W);
    router_kernel<<<N / BM, THREADS, SMEM_BYTES>>>(x, probs, idx, wts);
    refine_kernel<<<64, 256>>>(x, W, idx, wts);
}